// round 2
// baseline (speedup 1.0000x reference)
#include <cuda_runtime.h>

// Problem constants
#define NB   32
#define C    4096
#define HW   784        // 28*28
#define HW4  196        // HW / 4 (float4 granularity)
#define NO   4          // output channels
#define CHUNKS 32
#define CC   (C / CHUNKS)   // 128 channels per chunk

// Scratch (no allocation allowed):
// per-chunk partial cams + final mean map
__device__ float g_part[CHUNKS * NB * NO * HW];  // 12.84 MB (L2-resident)
__device__ float g_mean[NB * HW];                // 100 KB

// ---------------------------------------------------------------------------
// Kernel 1: partial dot products, NO atomics.
// grid = (CHUNKS, NB), 224 threads (7 warps). Threads 0..195 each own one
// float4 (4 hw positions); loop CC channels; write partials to g_part.
// ---------------------------------------------------------------------------
__global__ __launch_bounds__(224) void k1_dot(const float* __restrict__ x,
                                              const float* __restrict__ w) {
    const int cchunk = blockIdx.x;
    const int n      = blockIdx.y;
    const int tid    = threadIdx.x;

    __shared__ float sw[NO][CC];
    for (int i = tid; i < NO * CC; i += 224) {
        int o = i / CC, c = i % CC;
        sw[o][c] = w[o * C + cchunk * CC + c];
    }
    __syncthreads();

    if (tid >= HW4) return;

    float a00 = 0.f, a01 = 0.f, a02 = 0.f, a03 = 0.f;
    float a10 = 0.f, a11 = 0.f, a12 = 0.f, a13 = 0.f;
    float a20 = 0.f, a21 = 0.f, a22 = 0.f, a23 = 0.f;
    float a30 = 0.f, a31 = 0.f, a32 = 0.f, a33 = 0.f;

    const float* xb = x + ((size_t)n * C + (size_t)cchunk * CC) * HW + tid * 4;

#pragma unroll 4
    for (int c = 0; c < CC; c++) {
        float4 xv = *(const float4*)(xb + (size_t)c * HW);
        float w0 = sw[0][c], w1 = sw[1][c], w2 = sw[2][c], w3 = sw[3][c];
        a00 += w0 * xv.x; a01 += w0 * xv.y; a02 += w0 * xv.z; a03 += w0 * xv.w;
        a10 += w1 * xv.x; a11 += w1 * xv.y; a12 += w1 * xv.z; a13 += w1 * xv.w;
        a20 += w2 * xv.x; a21 += w2 * xv.y; a22 += w2 * xv.z; a23 += w2 * xv.w;
        a30 += w3 * xv.x; a31 += w3 * xv.y; a32 += w3 * xv.z; a33 += w3 * xv.w;
    }

    const int hw = tid * 4;
    float* base = &g_part[(((size_t)cchunk * NB + n) * NO) * HW];
    *(float4*)(base + 0 * HW + hw) = make_float4(a00, a01, a02, a03);
    *(float4*)(base + 1 * HW + hw) = make_float4(a10, a11, a12, a13);
    *(float4*)(base + 2 * HW + hw) = make_float4(a20, a21, a22, a23);
    *(float4*)(base + 3 * HW + hw) = make_float4(a30, a31, a32, a33);
}

// ---------------------------------------------------------------------------
// Kernel 2: reduce chunk partials -> relu -> per-(n,o) max -> threshold ->
// mean-drop map. 32 blocks, 256 threads (196 active). All reads L2-resident.
// ---------------------------------------------------------------------------
__global__ __launch_bounds__(256) void k2_thresh(const float* __restrict__ gama_p) {
    const int n   = blockIdx.x;
    const int tid = threadIdx.x;
    const float gama = *gama_p;

    float v[NO][4];
    float lmax[NO] = {0.f, 0.f, 0.f, 0.f};   // relu outputs are >= 0

    const bool active = tid < HW4;
    if (active) {
        const int hw = tid * 4;
#pragma unroll
        for (int o = 0; o < NO; o++) {
            float sx = 0.f, sy = 0.f, sz = 0.f, sww = 0.f;
#pragma unroll 8
            for (int ch = 0; ch < CHUNKS; ch++) {
                const float* p = &g_part[(((size_t)ch * NB + n) * NO + o) * HW + hw];
                float4 cv = *(const float4*)p;
                sx += cv.x; sy += cv.y; sz += cv.z; sww += cv.w;
            }
            v[o][0] = fmaxf(sx, 0.f);
            v[o][1] = fmaxf(sy, 0.f);
            v[o][2] = fmaxf(sz, 0.f);
            v[o][3] = fmaxf(sww, 0.f);
            lmax[o] = fmaxf(fmaxf(v[o][0], v[o][1]), fmaxf(v[o][2], v[o][3]));
        }
    }

    __shared__ float smax[NO][256];
#pragma unroll
    for (int o = 0; o < NO; o++) smax[o][tid] = lmax[o];
    __syncthreads();
    for (int s = 128; s > 0; s >>= 1) {
        if (tid < s) {
#pragma unroll
            for (int o = 0; o < NO; o++)
                smax[o][tid] = fmaxf(smax[o][tid], smax[o][tid + s]);
        }
        __syncthreads();
    }

    if (active) {
        float thr0 = smax[0][0] * gama;
        float thr1 = smax[1][0] * gama;
        float thr2 = smax[2][0] * gama;
        float thr3 = smax[3][0] * gama;
        float4 m;
        m.x = ((v[0][0] > thr0 ? 0.f : v[0][0]) + (v[1][0] > thr1 ? 0.f : v[1][0]) +
               (v[2][0] > thr2 ? 0.f : v[2][0]) + (v[3][0] > thr3 ? 0.f : v[3][0])) * 0.25f;
        m.y = ((v[0][1] > thr0 ? 0.f : v[0][1]) + (v[1][1] > thr1 ? 0.f : v[1][1]) +
               (v[2][1] > thr2 ? 0.f : v[2][1]) + (v[3][1] > thr3 ? 0.f : v[3][1])) * 0.25f;
        m.z = ((v[0][2] > thr0 ? 0.f : v[0][2]) + (v[1][2] > thr1 ? 0.f : v[1][2]) +
               (v[2][2] > thr2 ? 0.f : v[2][2]) + (v[3][2] > thr3 ? 0.f : v[3][2])) * 0.25f;
        m.w = ((v[0][3] > thr0 ? 0.f : v[0][3]) + (v[1][3] > thr1 ? 0.f : v[1][3]) +
               (v[2][3] > thr2 ? 0.f : v[2][3]) + (v[3][3] > thr3 ? 0.f : v[3][3])) * 0.25f;
        *(float4*)&g_mean[(size_t)n * HW + tid * 4] = m;
    }
}

// ---------------------------------------------------------------------------
// Kernel 3: out = x * mean[n, hw]. Grid-stride, unroll 4 for MLP batching.
// 822 MB HBM traffic; mean map is L2-resident.
// ---------------------------------------------------------------------------
#define K3_BLOCKS 1184   // 148 * 8
__global__ __launch_bounds__(256) void k3_mul(const float* __restrict__ x,
                                              float* __restrict__ out) {
    const unsigned int total4 = (unsigned int)NB * C * HW4;  // 25,690,112
    const unsigned int stride = K3_BLOCKS * 256;
    unsigned int i4 = blockIdx.x * 256 + threadIdx.x;

#pragma unroll 4
    for (; i4 < total4; i4 += stride) {
        unsigned int hw4 = i4 % HW4;
        unsigned int n   = i4 / (HW4 * C);

        float4 xv = ((const float4*)x)[i4];
        float4 m  = *(const float4*)&g_mean[(size_t)n * HW + hw4 * 4];
        float4 r;
        r.x = xv.x * m.x;
        r.y = xv.y * m.y;
        r.z = xv.z * m.z;
        r.w = xv.w * m.w;
        ((float4*)out)[i4] = r;
    }
}

// ---------------------------------------------------------------------------
extern "C" void kernel_launch(void* const* d_in, const int* in_sizes, int n_in,
                              void* d_out, int out_size) {
    const float* x    = (const float*)d_in[0];
    const float* w    = (const float*)d_in[1];
    const float* gama = (const float*)d_in[2];
    float* out        = (float*)d_out;

    // pass 1: partial dot products (no atomics, no zero-init needed)
    {
        dim3 grid(CHUNKS, NB);
        k1_dot<<<grid, 224>>>(x, w);
    }
    // reduce partials + threshold + mean map
    k2_thresh<<<NB, 256>>>(gama);
    // pass 2: elementwise multiply
    k3_mul<<<K3_BLOCKS, 256>>>(x, out);
}

// round 4
// speedup vs baseline: 1.3200x; 1.3200x over previous
#include <cuda_runtime.h>

// Problem constants
#define NB   32
#define C    4096
#define HW   784        // 28*28
#define HW4  196        // HW / 4 (float4 granularity)
#define NO   4          // output channels
#define CHUNKS 32
#define CC   (C / CHUNKS)   // 128 channels per chunk

// Scratch (no allocation allowed)
__device__ float g_part[CHUNKS * NB * NO * HW];  // 12.84 MB partials (L2)
__device__ float g_cams[NB * NO * HW];           // 401 KB relu'd cams
__device__ float g_max[NB * NO];                 // per-(n,o) spatial max
__device__ float g_mean[NB * HW];                // 100 KB mean map

// ---------------------------------------------------------------------------
// Kernel 1: partial dot products, no atomics. grid=(CHUNKS, NB), 256 threads.
// Threads 0..195 own one float4 of hw; loop CC channels; weights transposed
// in smem as float4 (1 LDS.128/channel). unroll 8 -> 8 independent LDG.128.
// ---------------------------------------------------------------------------
__global__ __launch_bounds__(256, 4) void k1_dot(const float* __restrict__ x,
                                                 const float* __restrict__ w) {
    const int cchunk = blockIdx.x;
    const int n      = blockIdx.y;
    const int tid    = threadIdx.x;

    __shared__ float4 sw[CC];   // transposed: sw[c] = {w0,w1,w2,w3}
    if (tid < CC) {
        int c = cchunk * CC + tid;
        sw[tid] = make_float4(w[0 * C + c], w[1 * C + c],
                              w[2 * C + c], w[3 * C + c]);
    }
    __syncthreads();

    if (tid >= HW4) return;

    float a00 = 0.f, a01 = 0.f, a02 = 0.f, a03 = 0.f;
    float a10 = 0.f, a11 = 0.f, a12 = 0.f, a13 = 0.f;
    float a20 = 0.f, a21 = 0.f, a22 = 0.f, a23 = 0.f;
    float a30 = 0.f, a31 = 0.f, a32 = 0.f, a33 = 0.f;

    const float* xb = x + ((size_t)n * C + (size_t)cchunk * CC) * HW + tid * 4;

#pragma unroll 8
    for (int c = 0; c < CC; c++) {
        float4 xv = *(const float4*)(xb + (size_t)c * HW);
        float4 wv = sw[c];
        a00 += wv.x * xv.x; a01 += wv.x * xv.y; a02 += wv.x * xv.z; a03 += wv.x * xv.w;
        a10 += wv.y * xv.x; a11 += wv.y * xv.y; a12 += wv.y * xv.z; a13 += wv.y * xv.w;
        a20 += wv.z * xv.x; a21 += wv.z * xv.y; a22 += wv.z * xv.z; a23 += wv.z * xv.w;
        a30 += wv.w * xv.x; a31 += wv.w * xv.y; a32 += wv.w * xv.z; a33 += wv.w * xv.w;
    }

    const int hw = tid * 4;
    float* base = &g_part[(((size_t)cchunk * NB + n) * NO) * HW];
    *(float4*)(base + 0 * HW + hw) = make_float4(a00, a01, a02, a03);
    *(float4*)(base + 1 * HW + hw) = make_float4(a10, a11, a12, a13);
    *(float4*)(base + 2 * HW + hw) = make_float4(a20, a21, a22, a23);
    *(float4*)(base + 3 * HW + hw) = make_float4(a30, a31, a32, a33);
}

// ---------------------------------------------------------------------------
// Kernel 2a: parallel chunk reduction + relu + per-(n,o) spatial max.
// grid = NB*NO = 128 blocks, 256 threads (power-of-2 reduction tree).
// ---------------------------------------------------------------------------
__global__ __launch_bounds__(256) void k2a_reduce() {
    const int no  = blockIdx.x;          // 0..127
    const int n   = no >> 2;
    const int o   = no & 3;
    const int tid = threadIdx.x;

    float lmax = 0.f;                    // relu outputs >= 0
    if (tid < HW4) {
        const int hw = tid * 4;
        float sx = 0.f, sy = 0.f, sz = 0.f, sw_ = 0.f;
#pragma unroll 8
        for (int ch = 0; ch < CHUNKS; ch++) {
            const float* p = &g_part[(((size_t)ch * NB + n) * NO + o) * HW + hw];
            float4 cv = *(const float4*)p;
            sx += cv.x; sy += cv.y; sz += cv.z; sw_ += cv.w;
        }
        sx = fmaxf(sx, 0.f); sy = fmaxf(sy, 0.f);
        sz = fmaxf(sz, 0.f); sw_ = fmaxf(sw_, 0.f);
        *(float4*)&g_cams[((size_t)n * NO + o) * HW + hw] = make_float4(sx, sy, sz, sw_);
        lmax = fmaxf(fmaxf(sx, sy), fmaxf(sz, sw_));
    }

    __shared__ float smax[256];
    smax[tid] = lmax;
    __syncthreads();
#pragma unroll
    for (int s = 128; s > 0; s >>= 1) {
        if (tid < s) smax[tid] = fmaxf(smax[tid], smax[tid + s]);
        __syncthreads();
    }
    if (tid == 0) g_max[no] = smax[0];
}

// ---------------------------------------------------------------------------
// Kernel 2b: threshold + mean-drop map. 32 blocks, tiny.
// ---------------------------------------------------------------------------
__global__ __launch_bounds__(224) void k2b_mean(const float* __restrict__ gama_p) {
    const int n   = blockIdx.x;
    const int tid = threadIdx.x;
    if (tid >= HW4) return;

    const float gama = *gama_p;
    const float thr0 = g_max[n * NO + 0] * gama;
    const float thr1 = g_max[n * NO + 1] * gama;
    const float thr2 = g_max[n * NO + 2] * gama;
    const float thr3 = g_max[n * NO + 3] * gama;

    const int hw = tid * 4;
    float4 c0 = *(const float4*)&g_cams[((size_t)n * NO + 0) * HW + hw];
    float4 c1 = *(const float4*)&g_cams[((size_t)n * NO + 1) * HW + hw];
    float4 c2 = *(const float4*)&g_cams[((size_t)n * NO + 2) * HW + hw];
    float4 c3 = *(const float4*)&g_cams[((size_t)n * NO + 3) * HW + hw];

    float4 m;
    m.x = ((c0.x > thr0 ? 0.f : c0.x) + (c1.x > thr1 ? 0.f : c1.x) +
           (c2.x > thr2 ? 0.f : c2.x) + (c3.x > thr3 ? 0.f : c3.x)) * 0.25f;
    m.y = ((c0.y > thr0 ? 0.f : c0.y) + (c1.y > thr1 ? 0.f : c1.y) +
           (c2.y > thr2 ? 0.f : c2.y) + (c3.y > thr3 ? 0.f : c3.y)) * 0.25f;
    m.z = ((c0.z > thr0 ? 0.f : c0.z) + (c1.z > thr1 ? 0.f : c1.z) +
           (c2.z > thr2 ? 0.f : c2.z) + (c3.z > thr3 ? 0.f : c3.z)) * 0.25f;
    m.w = ((c0.w > thr0 ? 0.f : c0.w) + (c1.w > thr1 ? 0.f : c1.w) +
           (c2.w > thr2 ? 0.f : c2.w) + (c3.w > thr3 ? 0.f : c3.w)) * 0.25f;
    *(float4*)&g_mean[(size_t)n * HW + hw] = m;
}

// ---------------------------------------------------------------------------
// Kernel 3: out = x * mean[n, hw]. Grid-stride, unroll 4. (81% DRAM)
// ---------------------------------------------------------------------------
#define K3_BLOCKS 1184   // 148 * 8
__global__ __launch_bounds__(256) void k3_mul(const float* __restrict__ x,
                                              float* __restrict__ out) {
    const unsigned int total4 = (unsigned int)NB * C * HW4;  // 25,690,112
    const unsigned int stride = K3_BLOCKS * 256;
    unsigned int i4 = blockIdx.x * 256 + threadIdx.x;

#pragma unroll 4
    for (; i4 < total4; i4 += stride) {
        unsigned int hw4 = i4 % HW4;
        unsigned int n   = i4 / (HW4 * C);

        float4 xv = ((const float4*)x)[i4];
        float4 m  = *(const float4*)&g_mean[(size_t)n * HW + hw4 * 4];
        float4 r;
        r.x = xv.x * m.x;
        r.y = xv.y * m.y;
        r.z = xv.z * m.z;
        r.w = xv.w * m.w;
        ((float4*)out)[i4] = r;
    }
}

// ---------------------------------------------------------------------------
extern "C" void kernel_launch(void* const* d_in, const int* in_sizes, int n_in,
                              void* d_out, int out_size) {
    const float* x    = (const float*)d_in[0];
    const float* w    = (const float*)d_in[1];
    const float* gama = (const float*)d_in[2];
    float* out        = (float*)d_out;

    {
        dim3 grid(CHUNKS, NB);
        k1_dot<<<grid, 256>>>(x, w);
    }
    k2a_reduce<<<NB * NO, 256>>>();
    k2b_mean<<<NB, 224>>>(gama);
    k3_mul<<<K3_BLOCKS, 256>>>(x, out);
}

// round 5
// speedup vs baseline: 1.3467x; 1.0203x over previous
#include <cuda_runtime.h>

// Problem constants
#define NB   32
#define C    4096
#define HW   784        // 28*28
#define HW4  196        // HW / 4 (float4 granularity)
#define NO   4          // output channels
#define CHUNKS 37       // 37*32 = 1184 blocks = 2 * (148 SMs * 4 blocks/SM): zero tail
#define CCMAX 111       // ceil(4096/37)

// Scratch (no allocation allowed)
__device__ float g_part[CHUNKS * NB * NO * HW];  // 14.86 MB partials (L2)
__device__ float g_cams[NB * NO * HW];           // 401 KB relu'd cams
__device__ float g_max[NB * NO];                 // per-(n,o) spatial max
__device__ float g_mean[NB * HW];                // 100 KB mean map

// ---------------------------------------------------------------------------
// Kernel 1: partial dot products, no atomics. grid=(CHUNKS, NB), 256 threads.
// Variable chunk bounds [chunk*C/37, (chunk+1)*C/37). Weights transposed in
// smem as float4 (1 LDS.128/channel); unroll 8 -> 8 independent LDG.128.
// ---------------------------------------------------------------------------
__global__ __launch_bounds__(256, 4) void k1_dot(const float* __restrict__ x,
                                                 const float* __restrict__ w) {
    const int cchunk = blockIdx.x;
    const int n      = blockIdx.y;
    const int tid    = threadIdx.x;

    const int cbeg = (cchunk * C) / CHUNKS;
    const int cend = ((cchunk + 1) * C) / CHUNKS;
    const int cc   = cend - cbeg;          // 110 or 111

    __shared__ float4 sw[CCMAX];           // transposed: sw[c] = {w0,w1,w2,w3}
    if (tid < cc) {
        int c = cbeg + tid;
        sw[tid] = make_float4(w[0 * C + c], w[1 * C + c],
                              w[2 * C + c], w[3 * C + c]);
    }
    __syncthreads();

    if (tid >= HW4) return;

    float a00 = 0.f, a01 = 0.f, a02 = 0.f, a03 = 0.f;
    float a10 = 0.f, a11 = 0.f, a12 = 0.f, a13 = 0.f;
    float a20 = 0.f, a21 = 0.f, a22 = 0.f, a23 = 0.f;
    float a30 = 0.f, a31 = 0.f, a32 = 0.f, a33 = 0.f;

    const float* xb = x + ((size_t)n * C + (size_t)cbeg) * HW + tid * 4;

#pragma unroll 8
    for (int c = 0; c < cc; c++) {
        float4 xv = *(const float4*)(xb + (size_t)c * HW);
        float4 wv = sw[c];
        a00 += wv.x * xv.x; a01 += wv.x * xv.y; a02 += wv.x * xv.z; a03 += wv.x * xv.w;
        a10 += wv.y * xv.x; a11 += wv.y * xv.y; a12 += wv.y * xv.z; a13 += wv.y * xv.w;
        a20 += wv.z * xv.x; a21 += wv.z * xv.y; a22 += wv.z * xv.z; a23 += wv.z * xv.w;
        a30 += wv.w * xv.x; a31 += wv.w * xv.y; a32 += wv.w * xv.z; a33 += wv.w * xv.w;
    }

    const int hw = tid * 4;
    float* base = &g_part[(((size_t)cchunk * NB + n) * NO) * HW];
    *(float4*)(base + 0 * HW + hw) = make_float4(a00, a01, a02, a03);
    *(float4*)(base + 1 * HW + hw) = make_float4(a10, a11, a12, a13);
    *(float4*)(base + 2 * HW + hw) = make_float4(a20, a21, a22, a23);
    *(float4*)(base + 3 * HW + hw) = make_float4(a30, a31, a32, a33);
}

// ---------------------------------------------------------------------------
// Kernel 2a: parallel chunk reduction + relu + per-(n,o) spatial max.
// grid = NB*NO = 128 blocks, 256 threads (power-of-2 reduction tree).
// ---------------------------------------------------------------------------
__global__ __launch_bounds__(256) void k2a_reduce() {
    const int no  = blockIdx.x;          // 0..127
    const int n   = no >> 2;
    const int o   = no & 3;
    const int tid = threadIdx.x;

    float lmax = 0.f;                    // relu outputs >= 0
    if (tid < HW4) {
        const int hw = tid * 4;
        float sx = 0.f, sy = 0.f, sz = 0.f, sw_ = 0.f;
#pragma unroll
        for (int ch = 0; ch < CHUNKS; ch++) {
            const float* p = &g_part[(((size_t)ch * NB + n) * NO + o) * HW + hw];
            float4 cv = *(const float4*)p;
            sx += cv.x; sy += cv.y; sz += cv.z; sw_ += cv.w;
        }
        sx = fmaxf(sx, 0.f); sy = fmaxf(sy, 0.f);
        sz = fmaxf(sz, 0.f); sw_ = fmaxf(sw_, 0.f);
        *(float4*)&g_cams[((size_t)n * NO + o) * HW + hw] = make_float4(sx, sy, sz, sw_);
        lmax = fmaxf(fmaxf(sx, sy), fmaxf(sz, sw_));
    }

    __shared__ float smax[256];
    smax[tid] = lmax;
    __syncthreads();
#pragma unroll
    for (int s = 128; s > 0; s >>= 1) {
        if (tid < s) smax[tid] = fmaxf(smax[tid], smax[tid + s]);
        __syncthreads();
    }
    if (tid == 0) g_max[no] = smax[0];
}

// ---------------------------------------------------------------------------
// Kernel 2b: threshold + mean-drop map. 32 blocks, tiny.
// ---------------------------------------------------------------------------
__global__ __launch_bounds__(224) void k2b_mean(const float* __restrict__ gama_p) {
    const int n   = blockIdx.x;
    const int tid = threadIdx.x;
    if (tid >= HW4) return;

    const float gama = *gama_p;
    const float thr0 = g_max[n * NO + 0] * gama;
    const float thr1 = g_max[n * NO + 1] * gama;
    const float thr2 = g_max[n * NO + 2] * gama;
    const float thr3 = g_max[n * NO + 3] * gama;

    const int hw = tid * 4;
    float4 c0 = *(const float4*)&g_cams[((size_t)n * NO + 0) * HW + hw];
    float4 c1 = *(const float4*)&g_cams[((size_t)n * NO + 1) * HW + hw];
    float4 c2 = *(const float4*)&g_cams[((size_t)n * NO + 2) * HW + hw];
    float4 c3 = *(const float4*)&g_cams[((size_t)n * NO + 3) * HW + hw];

    float4 m;
    m.x = ((c0.x > thr0 ? 0.f : c0.x) + (c1.x > thr1 ? 0.f : c1.x) +
           (c2.x > thr2 ? 0.f : c2.x) + (c3.x > thr3 ? 0.f : c3.x)) * 0.25f;
    m.y = ((c0.y > thr0 ? 0.f : c0.y) + (c1.y > thr1 ? 0.f : c1.y) +
           (c2.y > thr2 ? 0.f : c2.y) + (c3.y > thr3 ? 0.f : c3.y)) * 0.25f;
    m.z = ((c0.z > thr0 ? 0.f : c0.z) + (c1.z > thr1 ? 0.f : c1.z) +
           (c2.z > thr2 ? 0.f : c2.z) + (c3.z > thr3 ? 0.f : c3.z)) * 0.25f;
    m.w = ((c0.w > thr0 ? 0.f : c0.w) + (c1.w > thr1 ? 0.f : c1.w) +
           (c2.w > thr2 ? 0.f : c2.w) + (c3.w > thr3 ? 0.f : c3.w)) * 0.25f;
    *(float4*)&g_mean[(size_t)n * HW + hw] = m;
}

// ---------------------------------------------------------------------------
// Kernel 3: out = x * mean[n, hw]. Flat one-float4-per-thread (R1 form:
// 120.7us @ 81.2% DRAM — fastest measured variant).
// ---------------------------------------------------------------------------
__global__ __launch_bounds__(256) void k3_mul(const float* __restrict__ x,
                                              float* __restrict__ out) {
    unsigned int i4 = blockIdx.x * blockDim.x + threadIdx.x;
    const unsigned int total4 = (unsigned int)NB * C * HW4;  // 25,690,112
    if (i4 >= total4) return;

    unsigned int hw4 = i4 % HW4;
    unsigned int nc  = i4 / HW4;
    unsigned int n   = nc / C;

    float4 xv = ((const float4*)x)[i4];
    float4 m  = *(const float4*)&g_mean[(size_t)n * HW + hw4 * 4];
    float4 r;
    r.x = xv.x * m.x;
    r.y = xv.y * m.y;
    r.z = xv.z * m.z;
    r.w = xv.w * m.w;
    ((float4*)out)[i4] = r;
}

// ---------------------------------------------------------------------------
extern "C" void kernel_launch(void* const* d_in, const int* in_sizes, int n_in,
                              void* d_out, int out_size) {
    const float* x    = (const float*)d_in[0];
    const float* w    = (const float*)d_in[1];
    const float* gama = (const float*)d_in[2];
    float* out        = (float*)d_out;

    {
        dim3 grid(CHUNKS, NB);
        k1_dot<<<grid, 256>>>(x, w);
    }
    k2a_reduce<<<NB * NO, 256>>>();
    k2b_mean<<<NB, 224>>>(gama);
    {
        unsigned int total4 = (unsigned int)NB * C * HW4;
        k3_mul<<<(total4 + 255) / 256, 256>>>(x, out);
    }
}

// round 6
// speedup vs baseline: 1.3657x; 1.0141x over previous
#include <cuda_runtime.h>

// Problem constants
#define NB   32
#define C    4096
#define HW   784        // 28*28
#define HW4  196        // HW / 4 (float4 granularity)
#define NO   4          // output channels
#define CHUNKS 37       // 37*32 = 1184 blocks = 2 * (148 SMs * 4 blocks/SM): zero tail
#define CCMAX 111       // ceil(4096/37)

// Scratch (no allocation allowed)
__device__ float g_part[CHUNKS * NB * NO * HW];  // 14.86 MB partials (L2)
__device__ float g_cams[NB * NO * HW];           // 401 KB relu'd cams
__device__ float g_max[NB * NO];                 // per-(n,o) spatial max
__device__ float g_mean[NB * HW];                // 100 KB mean map

// ---------------------------------------------------------------------------
// Kernel 1: partial dot products, no atomics. grid=(CHUNKS, NB), 256 threads.
// x read with __ldcs (streaming: no reuse, don't pollute L2).
// Weights transposed in smem as float4; unroll 8 -> 8 independent LDG.128.
// ---------------------------------------------------------------------------
__global__ __launch_bounds__(256, 4) void k1_dot(const float* __restrict__ x,
                                                 const float* __restrict__ w) {
    const int cchunk = blockIdx.x;
    const int n      = blockIdx.y;
    const int tid    = threadIdx.x;

    const int cbeg = (cchunk * C) / CHUNKS;
    const int cend = ((cchunk + 1) * C) / CHUNKS;
    const int cc   = cend - cbeg;          // 110 or 111

    __shared__ float4 sw[CCMAX];           // transposed: sw[c] = {w0,w1,w2,w3}
    if (tid < cc) {
        int c = cbeg + tid;
        sw[tid] = make_float4(w[0 * C + c], w[1 * C + c],
                              w[2 * C + c], w[3 * C + c]);
    }
    __syncthreads();

    if (tid >= HW4) return;

    float a00 = 0.f, a01 = 0.f, a02 = 0.f, a03 = 0.f;
    float a10 = 0.f, a11 = 0.f, a12 = 0.f, a13 = 0.f;
    float a20 = 0.f, a21 = 0.f, a22 = 0.f, a23 = 0.f;
    float a30 = 0.f, a31 = 0.f, a32 = 0.f, a33 = 0.f;

    const float4* xb = (const float4*)(x + ((size_t)n * C + (size_t)cbeg) * HW) + tid;
    const size_t hw4stride = HW4;

#pragma unroll 8
    for (int c = 0; c < cc; c++) {
        float4 xv = __ldcs(xb + (size_t)c * hw4stride);
        float4 wv = sw[c];
        a00 += wv.x * xv.x; a01 += wv.x * xv.y; a02 += wv.x * xv.z; a03 += wv.x * xv.w;
        a10 += wv.y * xv.x; a11 += wv.y * xv.y; a12 += wv.y * xv.z; a13 += wv.y * xv.w;
        a20 += wv.z * xv.x; a21 += wv.z * xv.y; a22 += wv.z * xv.z; a23 += wv.z * xv.w;
        a30 += wv.w * xv.x; a31 += wv.w * xv.y; a32 += wv.w * xv.z; a33 += wv.w * xv.w;
    }

    const int hw = tid * 4;
    float* base = &g_part[(((size_t)cchunk * NB + n) * NO) * HW];
    *(float4*)(base + 0 * HW + hw) = make_float4(a00, a01, a02, a03);
    *(float4*)(base + 1 * HW + hw) = make_float4(a10, a11, a12, a13);
    *(float4*)(base + 2 * HW + hw) = make_float4(a20, a21, a22, a23);
    *(float4*)(base + 3 * HW + hw) = make_float4(a30, a31, a32, a33);
}

// ---------------------------------------------------------------------------
// Kernel 2a: parallel chunk reduction + relu + per-(n,o) spatial max.
// grid = NB*NO = 128 blocks, 256 threads (power-of-2 reduction tree).
// ---------------------------------------------------------------------------
__global__ __launch_bounds__(256) void k2a_reduce() {
    const int no  = blockIdx.x;          // 0..127
    const int n   = no >> 2;
    const int o   = no & 3;
    const int tid = threadIdx.x;

    float lmax = 0.f;                    // relu outputs >= 0
    if (tid < HW4) {
        const int hw = tid * 4;
        float sx = 0.f, sy = 0.f, sz = 0.f, sw_ = 0.f;
#pragma unroll
        for (int ch = 0; ch < CHUNKS; ch++) {
            const float* p = &g_part[(((size_t)ch * NB + n) * NO + o) * HW + hw];
            float4 cv = *(const float4*)p;
            sx += cv.x; sy += cv.y; sz += cv.z; sw_ += cv.w;
        }
        sx = fmaxf(sx, 0.f); sy = fmaxf(sy, 0.f);
        sz = fmaxf(sz, 0.f); sw_ = fmaxf(sw_, 0.f);
        *(float4*)&g_cams[((size_t)n * NO + o) * HW + hw] = make_float4(sx, sy, sz, sw_);
        lmax = fmaxf(fmaxf(sx, sy), fmaxf(sz, sw_));
    }

    __shared__ float smax[256];
    smax[tid] = lmax;
    __syncthreads();
#pragma unroll
    for (int s = 128; s > 0; s >>= 1) {
        if (tid < s) smax[tid] = fmaxf(smax[tid], smax[tid + s]);
        __syncthreads();
    }
    if (tid == 0) g_max[no] = smax[0];
}

// ---------------------------------------------------------------------------
// Kernel 2b: threshold + mean-drop map. 32 blocks, tiny.
// ---------------------------------------------------------------------------
__global__ __launch_bounds__(224) void k2b_mean(const float* __restrict__ gama_p) {
    const int n   = blockIdx.x;
    const int tid = threadIdx.x;
    if (tid >= HW4) return;

    const float gama = *gama_p;
    const float thr0 = g_max[n * NO + 0] * gama;
    const float thr1 = g_max[n * NO + 1] * gama;
    const float thr2 = g_max[n * NO + 2] * gama;
    const float thr3 = g_max[n * NO + 3] * gama;

    const int hw = tid * 4;
    float4 c0 = *(const float4*)&g_cams[((size_t)n * NO + 0) * HW + hw];
    float4 c1 = *(const float4*)&g_cams[((size_t)n * NO + 1) * HW + hw];
    float4 c2 = *(const float4*)&g_cams[((size_t)n * NO + 2) * HW + hw];
    float4 c3 = *(const float4*)&g_cams[((size_t)n * NO + 3) * HW + hw];

    float4 m;
    m.x = ((c0.x > thr0 ? 0.f : c0.x) + (c1.x > thr1 ? 0.f : c1.x) +
           (c2.x > thr2 ? 0.f : c2.x) + (c3.x > thr3 ? 0.f : c3.x)) * 0.25f;
    m.y = ((c0.y > thr0 ? 0.f : c0.y) + (c1.y > thr1 ? 0.f : c1.y) +
           (c2.y > thr2 ? 0.f : c2.y) + (c3.y > thr3 ? 0.f : c3.y)) * 0.25f;
    m.z = ((c0.z > thr0 ? 0.f : c0.z) + (c1.z > thr1 ? 0.f : c1.z) +
           (c2.z > thr2 ? 0.f : c2.z) + (c3.z > thr3 ? 0.f : c3.z)) * 0.25f;
    m.w = ((c0.w > thr0 ? 0.f : c0.w) + (c1.w > thr1 ? 0.f : c1.w) +
           (c2.w > thr2 ? 0.f : c2.w) + (c3.w > thr3 ? 0.f : c3.w)) * 0.25f;
    *(float4*)&g_mean[(size_t)n * HW + hw] = m;
}

// ---------------------------------------------------------------------------
// Kernel 3: out = x * mean[n, hw]. Flat one-float4-per-thread.
// x via __ldcs (no reuse), out via __stcs (never re-read): keep L2 clean.
// ---------------------------------------------------------------------------
__global__ __launch_bounds__(256) void k3_mul(const float* __restrict__ x,
                                              float* __restrict__ out) {
    unsigned int i4 = blockIdx.x * blockDim.x + threadIdx.x;
    const unsigned int total4 = (unsigned int)NB * C * HW4;  // 25,690,112
    if (i4 >= total4) return;

    unsigned int hw4 = i4 % HW4;
    unsigned int nc  = i4 / HW4;
    unsigned int n   = nc / C;

    float4 xv = __ldcs((const float4*)x + i4);
    float4 m  = *(const float4*)&g_mean[(size_t)n * HW + hw4 * 4];
    float4 r;
    r.x = xv.x * m.x;
    r.y = xv.y * m.y;
    r.z = xv.z * m.z;
    r.w = xv.w * m.w;
    __stcs((float4*)out + i4, r);
}

// ---------------------------------------------------------------------------
extern "C" void kernel_launch(void* const* d_in, const int* in_sizes, int n_in,
                              void* d_out, int out_size) {
    const float* x    = (const float*)d_in[0];
    const float* w    = (const float*)d_in[1];
    const float* gama = (const float*)d_in[2];
    float* out        = (float*)d_out;

    {
        dim3 grid(CHUNKS, NB);
        k1_dot<<<grid, 256>>>(x, w);
    }
    k2a_reduce<<<NB * NO, 256>>>();
    k2b_mean<<<NB, 224>>>(gama);
    {
        unsigned int total4 = (unsigned int)NB * C * HW4;
        k3_mul<<<(total4 + 255) / 256, 256>>>(x, out);
    }
}

// round 7
// speedup vs baseline: 1.4016x; 1.0262x over previous
#include <cuda_runtime.h>

// Problem constants
#define NB    32
#define NBH   16        // per-branch batch half
#define C     4096
#define HW    784       // 28*28
#define HW4   196       // HW / 4 (float4 granularity)
#define NO    4         // output channels
#define CHUNKS 37       // 37*32 = 1184 blocks total = 2 * (148 SMs * 4 blocks/SM)
#define CCMAX 111       // ceil(4096/37)

// Scratch (no allocation allowed)
__device__ float g_part[CHUNKS * NB * NO * HW];  // 14.86 MB partials (L2)
__device__ float g_cams[NB * NO * HW];           // 401 KB relu'd cams
__device__ float g_max[NB * NO];                 // per-(n,o) spatial max
__device__ float g_mean[NB * HW];                // 100 KB mean map

// ---------------------------------------------------------------------------
// Kernel 1: partial dot products for one batch half. grid=(CHUNKS, NBH).
// x read with __ldcs; weights transposed in smem as float4; unroll 8.
// ---------------------------------------------------------------------------
__global__ __launch_bounds__(256, 4) void k1_dot(const float* __restrict__ x,
                                                 const float* __restrict__ w,
                                                 int n_base) {
    const int cchunk = blockIdx.x;
    const int n      = n_base + blockIdx.y;
    const int tid    = threadIdx.x;

    const int cbeg = (cchunk * C) / CHUNKS;
    const int cend = ((cchunk + 1) * C) / CHUNKS;
    const int cc   = cend - cbeg;          // 110 or 111

    __shared__ float4 sw[CCMAX];           // transposed: sw[c] = {w0,w1,w2,w3}
    if (tid < cc) {
        int c = cbeg + tid;
        sw[tid] = make_float4(w[0 * C + c], w[1 * C + c],
                              w[2 * C + c], w[3 * C + c]);
    }
    __syncthreads();

    if (tid >= HW4) return;

    float a00 = 0.f, a01 = 0.f, a02 = 0.f, a03 = 0.f;
    float a10 = 0.f, a11 = 0.f, a12 = 0.f, a13 = 0.f;
    float a20 = 0.f, a21 = 0.f, a22 = 0.f, a23 = 0.f;
    float a30 = 0.f, a31 = 0.f, a32 = 0.f, a33 = 0.f;

    const float4* xb = (const float4*)(x + ((size_t)n * C + (size_t)cbeg) * HW) + tid;

#pragma unroll 8
    for (int c = 0; c < cc; c++) {
        float4 xv = __ldcs(xb + (size_t)c * HW4);
        float4 wv = sw[c];
        a00 += wv.x * xv.x; a01 += wv.x * xv.y; a02 += wv.x * xv.z; a03 += wv.x * xv.w;
        a10 += wv.y * xv.x; a11 += wv.y * xv.y; a12 += wv.y * xv.z; a13 += wv.y * xv.w;
        a20 += wv.z * xv.x; a21 += wv.z * xv.y; a22 += wv.z * xv.z; a23 += wv.z * xv.w;
        a30 += wv.w * xv.x; a31 += wv.w * xv.y; a32 += wv.w * xv.z; a33 += wv.w * xv.w;
    }

    const int hw = tid * 4;
    float* base = &g_part[(((size_t)cchunk * NB + n) * NO) * HW];
    *(float4*)(base + 0 * HW + hw) = make_float4(a00, a01, a02, a03);
    *(float4*)(base + 1 * HW + hw) = make_float4(a10, a11, a12, a13);
    *(float4*)(base + 2 * HW + hw) = make_float4(a20, a21, a22, a23);
    *(float4*)(base + 3 * HW + hw) = make_float4(a30, a31, a32, a33);
}

// ---------------------------------------------------------------------------
// Kernel 2a: chunk reduction + relu + per-(n,o) max for one half.
// grid = NBH*NO = 64 blocks, 256 threads (power-of-2 tree).
// ---------------------------------------------------------------------------
__global__ __launch_bounds__(256) void k2a_reduce(int n_base) {
    const int no  = n_base * NO + blockIdx.x;
    const int n   = no >> 2;
    const int o   = no & 3;
    const int tid = threadIdx.x;

    float lmax = 0.f;                    // relu outputs >= 0
    if (tid < HW4) {
        const int hw = tid * 4;
        float sx = 0.f, sy = 0.f, sz = 0.f, sw_ = 0.f;
#pragma unroll
        for (int ch = 0; ch < CHUNKS; ch++) {
            const float* p = &g_part[(((size_t)ch * NB + n) * NO + o) * HW + hw];
            float4 cv = *(const float4*)p;
            sx += cv.x; sy += cv.y; sz += cv.z; sw_ += cv.w;
        }
        sx = fmaxf(sx, 0.f); sy = fmaxf(sy, 0.f);
        sz = fmaxf(sz, 0.f); sw_ = fmaxf(sw_, 0.f);
        *(float4*)&g_cams[((size_t)n * NO + o) * HW + hw] = make_float4(sx, sy, sz, sw_);
        lmax = fmaxf(fmaxf(sx, sy), fmaxf(sz, sw_));
    }

    __shared__ float smax[256];
    smax[tid] = lmax;
    __syncthreads();
#pragma unroll
    for (int s = 128; s > 0; s >>= 1) {
        if (tid < s) smax[tid] = fmaxf(smax[tid], smax[tid + s]);
        __syncthreads();
    }
    if (tid == 0) g_max[no] = smax[0];
}

// ---------------------------------------------------------------------------
// Kernel 2b: threshold + mean-drop map for one half. NBH blocks, tiny.
// ---------------------------------------------------------------------------
__global__ __launch_bounds__(224) void k2b_mean(const float* __restrict__ gama_p,
                                                int n_base) {
    const int n   = n_base + blockIdx.x;
    const int tid = threadIdx.x;
    if (tid >= HW4) return;

    const float gama = *gama_p;
    const float thr0 = g_max[n * NO + 0] * gama;
    const float thr1 = g_max[n * NO + 1] * gama;
    const float thr2 = g_max[n * NO + 2] * gama;
    const float thr3 = g_max[n * NO + 3] * gama;

    const int hw = tid * 4;
    float4 c0 = *(const float4*)&g_cams[((size_t)n * NO + 0) * HW + hw];
    float4 c1 = *(const float4*)&g_cams[((size_t)n * NO + 1) * HW + hw];
    float4 c2 = *(const float4*)&g_cams[((size_t)n * NO + 2) * HW + hw];
    float4 c3 = *(const float4*)&g_cams[((size_t)n * NO + 3) * HW + hw];

    float4 m;
    m.x = ((c0.x > thr0 ? 0.f : c0.x) + (c1.x > thr1 ? 0.f : c1.x) +
           (c2.x > thr2 ? 0.f : c2.x) + (c3.x > thr3 ? 0.f : c3.x)) * 0.25f;
    m.y = ((c0.y > thr0 ? 0.f : c0.y) + (c1.y > thr1 ? 0.f : c1.y) +
           (c2.y > thr2 ? 0.f : c2.y) + (c3.y > thr3 ? 0.f : c3.y)) * 0.25f;
    m.z = ((c0.z > thr0 ? 0.f : c0.z) + (c1.z > thr1 ? 0.f : c1.z) +
           (c2.z > thr2 ? 0.f : c2.z) + (c3.z > thr3 ? 0.f : c3.z)) * 0.25f;
    m.w = ((c0.w > thr0 ? 0.f : c0.w) + (c1.w > thr1 ? 0.f : c1.w) +
           (c2.w > thr2 ? 0.f : c2.w) + (c3.w > thr3 ? 0.f : c3.w)) * 0.25f;
    *(float4*)&g_mean[(size_t)n * HW + hw] = m;
}

// ---------------------------------------------------------------------------
// Kernel 3: out = x * mean[n, hw] for one batch half. Flat float4/thread.
// ---------------------------------------------------------------------------
#define HALF4 ((unsigned int)NBH * C * HW4)   // 12,845,056 float4 per half
__global__ __launch_bounds__(256) void k3_mul(const float* __restrict__ x,
                                              float* __restrict__ out,
                                              unsigned int i4_base) {
    unsigned int idx = blockIdx.x * blockDim.x + threadIdx.x;
    if (idx >= HALF4) return;
    unsigned int i4 = i4_base + idx;

    unsigned int hw4 = i4 % HW4;
    unsigned int nc  = i4 / HW4;
    unsigned int n   = nc / C;

    float4 xv = __ldcs((const float4*)x + i4);
    float4 m  = *(const float4*)&g_mean[(size_t)n * HW + hw4 * 4];
    float4 r;
    r.x = xv.x * m.x;
    r.y = xv.y * m.y;
    r.z = xv.z * m.z;
    r.w = xv.w * m.w;
    __stcs((float4*)out + i4, r);
}

// ---------------------------------------------------------------------------
// Fork-join over two branches (graph-capturable: event fork/join on stream 0).
// Branch A: n 0..15 on stream 0.  Branch B: n 16..31 on side stream.
// ---------------------------------------------------------------------------
extern "C" void kernel_launch(void* const* d_in, const int* in_sizes, int n_in,
                              void* d_out, int out_size) {
    const float* x    = (const float*)d_in[0];
    const float* w    = (const float*)d_in[1];
    const float* gama = (const float*)d_in[2];
    float* out        = (float*)d_out;

    // Lazy one-time creation (correctness run precedes graph capture).
    static cudaStream_t s2 = nullptr;
    static cudaEvent_t ev_fork = nullptr, ev_join = nullptr;
    if (!s2) {
        cudaStreamCreateWithFlags(&s2, cudaStreamNonBlocking);
        cudaEventCreateWithFlags(&ev_fork, cudaEventDisableTiming);
        cudaEventCreateWithFlags(&ev_join, cudaEventDisableTiming);
    }

    // Fork
    cudaEventRecord(ev_fork, 0);
    cudaStreamWaitEvent(s2, ev_fork, 0);

    dim3 g1(CHUNKS, NBH);
    const unsigned int k3_blocks = (HALF4 + 255) / 256;

    // Branch A (n 0..15) on the capturing/legacy stream
    k1_dot<<<g1, 256>>>(x, w, 0);
    k2a_reduce<<<NBH * NO, 256>>>(0);
    k2b_mean<<<NBH, 224>>>(gama, 0);
    k3_mul<<<k3_blocks, 256>>>(x, out, 0u);

    // Branch B (n 16..31) on the side stream
    k1_dot<<<g1, 256, 0, s2>>>(x, w, NBH);
    k2a_reduce<<<NBH * NO, 256, 0, s2>>>(NBH);
    k2b_mean<<<NBH, 224, 0, s2>>>(gama, NBH);
    k3_mul<<<k3_blocks, 256, 0, s2>>>(x, out, HALF4);

    // Join
    cudaEventRecord(ev_join, s2);
    cudaStreamWaitEvent(0, ev_join, 0);
}